// round 7
// baseline (speedup 1.0000x reference)
#include <cuda_runtime.h>
#include <cuda_bf16.h>

#define N_NODES 50000
#define N_EDGES 200000
#define MUL 16
#define ALPHA 0.17677669529663687f
#define INV_SQRT3 0.5773502691896258f
#define AIS (ALPHA * INV_SQRT3)
#define BN_EPS 1e-5f
#define HS 132

typedef unsigned long long ull;
typedef unsigned int u32;

// ---------------- fp32x2 helpers (k_gemm1) ----------------
__device__ __forceinline__ ull ffma2(ull a, ull b, ull c) {
    ull d;
    asm("fma.rn.f32x2 %0, %1, %2, %3;" : "=l"(d) : "l"(a), "l"(b), "l"(c));
    return d;
}
__device__ __forceinline__ void unpack2(float& lo, float& hi, ull v) {
    asm("mov.b64 {%0, %1}, %2;" : "=f"(lo), "=f"(hi) : "l"(v));
}

// ---------------- mma / ldmatrix / cp.async (baseline PTX, no 'a' gates) ----------------
__device__ __forceinline__ u32 smem_u32(const void* p) {
    u32 a;
    asm("{ .reg .u64 t; cvta.to.shared.u64 t, %1; cvt.u32.u64 %0, t; }" : "=r"(a) : "l"(p));
    return a;
}
__device__ __forceinline__ void ldsm4(u32& r0, u32& r1, u32& r2, u32& r3, u32 addr) {
    asm volatile("ldmatrix.sync.aligned.m8n8.x4.shared.b16 {%0,%1,%2,%3}, [%4];"
                 : "=r"(r0), "=r"(r1), "=r"(r2), "=r"(r3) : "r"(addr));
}
__device__ __forceinline__ void mma16816(float* d, u32 a0, u32 a1, u32 a2, u32 a3,
                                         u32 b0, u32 b1) {
    asm volatile(
        "mma.sync.aligned.m16n8k16.row.col.f32.bf16.bf16.f32 "
        "{%0,%1,%2,%3}, {%4,%5,%6,%7}, {%8,%9}, {%0,%1,%2,%3};"
        : "+f"(d[0]), "+f"(d[1]), "+f"(d[2]), "+f"(d[3])
        : "r"(a0), "r"(a1), "r"(a2), "r"(a3), "r"(b0), "r"(b1));
}
__device__ __forceinline__ void cpasync16(u32 dst, const void* src) {
    asm volatile("cp.async.ca.shared.global [%0], [%1], 16;" :: "r"(dst), "l"(src) : "memory");
}
#define CP_COMMIT() asm volatile("cp.async.commit_group;" ::: "memory")
#define CP_WAIT0() asm volatile("cp.async.wait_group 0;" ::: "memory")

// ---------------- scratch ----------------
__device__ __align__(16) __nv_bfloat16 g_Hhi[N_EDGES * 64];
__device__ __align__(16) __nv_bfloat16 g_Hlo[N_EDGES * 64];
__device__ __align__(16) __nv_bfloat16 g_BThi[1024 * 64];
__device__ __align__(16) __nv_bfloat16 g_BTlo[1024 * 64];
__device__ float g_agg[N_NODES * 64];
__device__ float g_cnt[N_NODES];
__device__ float g_out[N_NODES * 64];
__device__ float g_stats[48];
__device__ float g_norm[48];

// ---------------- kernel 0: zero ----------------
__global__ void k_zero() {
    int idx = blockIdx.x * blockDim.x + threadIdx.x;
    int stride = gridDim.x * blockDim.x;
    for (int i = idx; i < N_NODES * 64; i += stride) g_agg[i] = 0.0f;
    for (int i = idx; i < N_NODES; i += stride) g_cnt[i] = 0.0f;
    if (idx < 48) g_stats[idx] = 0.0f;
}

// ---------------- kernel 0b: split W2^T into bf16 hi/lo ----------------
__global__ void k_wsplit(const float* __restrict__ w2) {
    int idx = blockIdx.x * blockDim.x + threadIdx.x;
    if (idx >= 64 * 1024) return;
    int j = idx >> 10, c = idx & 1023;
    float v = w2[idx];
    __nv_bfloat16 hi = __float2bfloat16(v);
    float lo = v - __bfloat162float(hi);
    g_BThi[c * 64 + j] = hi;
    g_BTlo[c * 64 + j] = __float2bfloat16(lo);
}

// ---------------- kernel 1: H = relu(EA @ W1 + b1), bf16 hi/lo output ----------------
__global__ __launch_bounds__(256) void k_gemm1(const float* __restrict__ ea,
                                               const float* __restrict__ w1,
                                               const float* __restrict__ b1) {
    extern __shared__ __align__(16) float smg[];
    float* eaT2 = smg;
    float* w1s = eaT2 + 64 * HS;
    int tid = threadIdx.x;
    int e0 = blockIdx.x * 64;

    for (int idx = tid; idx < 4096; idx += 256) {
        int e = idx >> 6, j = idx & 63;
        float v = ea[(e0 + e) * 64 + j];
        eaT2[j * HS + 2 * e] = v;
        eaT2[j * HS + 2 * e + 1] = v;
        w1s[idx] = w1[idx];
    }
    __syncthreads();

    int te = (tid >> 4) << 2;
    int tc = (tid & 15) << 2;
    ull acc2[4][2];
#pragma unroll
    for (int a = 0; a < 4; a++) { acc2[a][0] = 0ULL; acc2[a][1] = 0ULL; }

#pragma unroll 4
    for (int j = 0; j < 64; j++) {
        ulonglong2 e01 = *(const ulonglong2*)&eaT2[j * HS + 2 * te];
        ulonglong2 e23 = *(const ulonglong2*)&eaT2[j * HS + 2 * te + 4];
        ulonglong2 wq = *(const ulonglong2*)&w1s[j * 64 + tc];
        ull hd[4] = {e01.x, e01.y, e23.x, e23.y};
        ull wp[2] = {wq.x, wq.y};
#pragma unroll
        for (int a = 0; a < 4; a++)
#pragma unroll
            for (int p = 0; p < 2; p++) acc2[a][p] = ffma2(hd[a], wp[p], acc2[a][p]);
    }

    float bb[4] = {b1[tc], b1[tc + 1], b1[tc + 2], b1[tc + 3]};
#pragma unroll
    for (int a = 0; a < 4; a++) {
        float o[4];
        unpack2(o[0], o[1], acc2[a][0]);
        unpack2(o[2], o[3], acc2[a][1]);
        __nv_bfloat162 hh[2], ll[2];
#pragma unroll
        for (int q = 0; q < 4; q++) {
            float v = fmaxf(o[q] + bb[q], 0.0f);
            __nv_bfloat16 hi = __float2bfloat16(v);
            float lo = v - __bfloat162float(hi);
            if (q & 1) { hh[q >> 1].y = hi; ll[q >> 1].y = __float2bfloat16(lo); }
            else       { hh[q >> 1].x = hi; ll[q >> 1].x = __float2bfloat16(lo); }
        }
        int base = (e0 + te + a) * 64 + tc;
        *(__nv_bfloat162*)&g_Hhi[base] = hh[0];
        *(__nv_bfloat162*)&g_Hhi[base + 2] = hh[1];
        *(__nv_bfloat162*)&g_Hlo[base] = ll[0];
        *(__nv_bfloat162*)&g_Hlo[base + 2] = ll[1];
    }
}

// ---------------- kernel 2: mma.sync GEMM2 + TP + scatter ----------------
// 256 threads, 128 edges/block. Persistent A frags in registers; B slices
// cp.async double-buffered into the (dead after prologue) A staging region.
// 16 slices x 4 bq-groups of 16 cols; D = 8 regs, contraction per bq.
#define OFF_AB 0            // 36864: prologue A hi/lo; mainloop B dbl buf (2 x 18432)
#define OFF_CA 36864
#define OFF_CB 45312
#define OFF_CX 53760
#define OFF_CD 62208
#define OFF_B2 87552
#define OFF_SHS 91648
#define SMEM_TP 93696

__global__ __launch_bounds__(256, 2) void k_tp(const float* __restrict__ node_attr,
                                               const float* __restrict__ edge_sh,
                                               const float* __restrict__ b2,
                                               const int* __restrict__ edge_index) {
    extern __shared__ __align__(16) char smem[];
    float* cA = (float*)(smem + OFF_CA);
    float* cB = (float*)(smem + OFF_CB);
    float* cX = (float*)(smem + OFF_CX);
    float* cD = (float*)(smem + OFF_CD);
    float* b2s = (float*)(smem + OFF_B2);
    float* shs = (float*)(smem + OFF_SHS);
    __shared__ int srcs[128], dsts[128];

    int tid = threadIdx.x;
    int lane = tid & 31;
    int wid = tid >> 5;
    int e0 = blockIdx.x * 128;
    u32 sbase = smem_u32(smem);

    if (tid < 128) {
        int e = e0 + tid;
        bool val = e < N_EDGES;
        float4 sh = val ? ((const float4*)edge_sh)[e] : make_float4(0, 0, 0, 0);
        *(float4*)&shs[tid * 4] = sh;
        srcs[tid] = val ? edge_index[e] : 0;
        dsts[tid] = val ? edge_index[N_EDGES + e] : -1;
    }
    for (int idx = tid; idx < 1024; idx += 256) b2s[idx] = b2[idx];
    __syncthreads();

    // A tiles (bf16 hi/lo) into overlay region, rows padded to 144B
    for (int idx = tid; idx < 1024; idx += 256) {
        int rr = idx >> 3, qq = idx & 7;
        int ge = e0 + rr;
        uint4 vh = make_uint4(0, 0, 0, 0), vl = vh;
        if (ge < N_EDGES) {
            vh = ((const uint4*)g_Hhi)[ge * 8 + qq];
            vl = ((const uint4*)g_Hlo)[ge * 8 + qq];
        }
        *(uint4*)(smem + OFF_AB + rr * 144 + qq * 16) = vh;
        *(uint4*)(smem + OFF_AB + 18432 + rr * 144 + qq * 16) = vl;
    }
    // coefficients [i][132e]
    for (int idx = tid; idx < 2048; idx += 256) {
        int e = idx >> 4, i = idx & 15;
        int d = dsts[e];
        float ss = shs[e * 4], s1 = shs[e * 4 + 1], s2 = shs[e * 4 + 2], s3 = shs[e * 4 + 3];
        float xs = 0, x0 = 0, x1 = 0, x2 = 0;
        if (d >= 0) {
            xs = node_attr[d * 64 + i];
            const float* xp = &node_attr[d * 64 + 16 + 3 * i];
            x0 = xp[0]; x1 = xp[1]; x2 = xp[2];
        }
        cA[i * 132 + e] = ALPHA * ss * xs;
        cX[i * 132 + e] = AIS * xs;
        cB[i * 132 + e] = AIS * (x0 * s1 + x1 * s2 + x2 * s3);
        cD[(0 * 16 + i) * 132 + e] = AIS * ss * x0;
        cD[(1 * 16 + i) * 132 + e] = AIS * ss * x1;
        cD[(2 * 16 + i) * 132 + e] = AIS * ss * x2;
    }
    __syncthreads();

    // persistent A fragments (hi/lo, 4 k-steps)
    u32 laneA = (u32)((wid * 16 + (lane & 7) + ((lane >> 3) & 1) * 8) * 144 +
                      ((lane >> 4) & 1) * 16);
    u32 aH[4][4], aL[4][4];
#pragma unroll
    for (int ks = 0; ks < 4; ks++) {
        ldsm4(aH[ks][0], aH[ks][1], aH[ks][2], aH[ks][3], sbase + OFF_AB + laneA + ks * 32);
        ldsm4(aL[ks][0], aL[ks][1], aL[ks][2], aL[ks][3],
              sbase + OFF_AB + 18432 + laneA + ks * 32);
    }
    __syncthreads();  // all warps done reading A before cp.async overwrites

    // issue B slice 0 into buffer 0
#pragma unroll 1
    for (int idx = tid; idx < 1024; idx += 256) {
        int half = idx >> 9, rem = idx & 511;
        int rr = rem >> 3, qq = rem & 7;
        const __nv_bfloat16* srcb = half ? g_BTlo : g_BThi;
        cpasync16(sbase + OFF_AB + half * 9216 + rr * 144 + qq * 16,
                  (const char*)srcb + rr * 128 + qq * 16);
    }
    CP_COMMIT();

    u32 laneB = (u32)(((lane & 7) + ((lane >> 4) & 1) * 8) * 144 + ((lane >> 3) & 1) * 16);
    int q = lane & 3;
    int r = lane >> 2;
    int el0 = wid * 16 + r;

    float accS[2][4], accR[2][4], accV[2][4][3];
#pragma unroll
    for (int m = 0; m < 2; m++)
#pragma unroll
        for (int s = 0; s < 4; s++) {
            accS[m][s] = 0; accR[m][s] = 0;
            accV[m][s][0] = 0; accV[m][s][1] = 0; accV[m][s][2] = 0;
        }

#pragma unroll 1
    for (int sl = 0; sl < 16; sl++) {
        int t = sl >> 2, g = sl & 3;
        int buf = sl & 1;
        CP_WAIT0();
        __syncthreads();  // slice sl ready in all lanes; compute(sl-1) fully done
        if (sl < 15) {
            int nb = (sl + 1) & 1;
            const char* bhp = (const char*)&g_BThi[(sl + 1) * 64 * 64];
            const char* blp = (const char*)&g_BTlo[(sl + 1) * 64 * 64];
#pragma unroll 1
            for (int idx = tid; idx < 1024; idx += 256) {
                int half = idx >> 9, rem = idx & 511;
                int rr = rem >> 3, qq = rem & 7;
                cpasync16(sbase + OFF_AB + nb * 18432 + half * 9216 + rr * 144 + qq * 16,
                          (half ? blp : bhp) + rr * 128 + qq * 16);
            }
            CP_COMMIT();
        }

        u32 bHbase = sbase + OFF_AB + buf * 18432 + laneB;
        u32 bLbase = bHbase + 9216;

#pragma unroll
        for (int bq = 0; bq < 4; bq++) {
            float d[8];
#pragma unroll
            for (int z = 0; z < 8; z++) d[z] = 0.0f;

#pragma unroll
            for (int ks = 0; ks < 4; ks++) {
                u32 bh0, bh1, bh2, bh3, bl0, bl1, bl2, bl3;
                ldsm4(bh0, bh1, bh2, bh3, bHbase + bq * 2304 + ks * 32);
                ldsm4(bl0, bl1, bl2, bl3, bLbase + bq * 2304 + ks * 32);
                mma16816(&d[0], aH[ks][0], aH[ks][1], aH[ks][2], aH[ks][3], bh0, bh1);
                mma16816(&d[4], aH[ks][0], aH[ks][1], aH[ks][2], aH[ks][3], bh2, bh3);
                mma16816(&d[0], aH[ks][0], aH[ks][1], aH[ks][2], aH[ks][3], bl0, bl1);
                mma16816(&d[4], aH[ks][0], aH[ks][1], aH[ks][2], aH[ks][3], bl2, bl3);
                mma16816(&d[0], aL[ks][0], aL[ks][1], aL[ks][2], aL[ks][3], bh0, bh1);
                mma16816(&d[4], aL[ks][0], aL[ks][1], aL[ks][2], aL[ks][3], bh2, bh3);
            }

            // contraction: i = 4g + bq is lane-invariant for this group
            int i = g * 4 + bq;
            int colb = g * 64 + bq * 16 + 2 * q;
            if (t < 3) {
                const float* cp = (t == 0) ? cA : (t == 1) ? cB : cX;
                float cv0 = cp[i * 132 + el0];
                float cv1 = cp[i * 132 + el0 + 8];
                float (*acc)[4] = (t == 2) ? accR : accS;
#pragma unroll
                for (int f = 0; f < 2; f++) {
                    float bb0 = b2s[t * 256 + colb + f * 8];
                    float bb1 = b2s[t * 256 + colb + f * 8 + 1];
                    acc[0][f * 2 + 0] += cv0 * (d[f * 4 + 0] + bb0);
                    acc[0][f * 2 + 1] += cv0 * (d[f * 4 + 1] + bb1);
                    acc[1][f * 2 + 0] += cv1 * (d[f * 4 + 2] + bb0);
                    acc[1][f * 2 + 1] += cv1 * (d[f * 4 + 3] + bb1);
                }
            } else {
                float cd0[3], cd1[3];
#pragma unroll
                for (int mm = 0; mm < 3; mm++) {
                    cd0[mm] = cD[(mm * 16 + i) * 132 + el0];
                    cd1[mm] = cD[(mm * 16 + i) * 132 + el0 + 8];
                }
#pragma unroll
                for (int f = 0; f < 2; f++) {
                    float bb0 = b2s[768 + colb + f * 8];
                    float bb1 = b2s[768 + colb + f * 8 + 1];
                    float w00 = d[f * 4 + 0] + bb0, w01 = d[f * 4 + 1] + bb1;
                    float w10 = d[f * 4 + 2] + bb0, w11 = d[f * 4 + 3] + bb1;
#pragma unroll
                    for (int mm = 0; mm < 3; mm++) {
                        accV[0][f * 2 + 0][mm] += cd0[mm] * w00;
                        accV[0][f * 2 + 1][mm] += cd0[mm] * w01;
                        accV[1][f * 2 + 0][mm] += cd1[mm] * w10;
                        accV[1][f * 2 + 1][mm] += cd1[mm] * w11;
                    }
                }
            }
        }
    }

    // scatter
#pragma unroll
    for (int m = 0; m < 2; m++) {
        int el = el0 + 8 * m;
        if (e0 + el < N_EDGES) {
            int src = srcs[el];
            float s1 = shs[el * 4 + 1], s2 = shs[el * 4 + 2], s3 = shs[el * 4 + 3];
#pragma unroll
            for (int sidx = 0; sidx < 4; sidx++) {
                int k = ((sidx >> 1) << 3) + 2 * q + (sidx & 1);
                atomicAdd(&g_agg[src * 64 + k], accS[m][sidx]);
                float rv = accR[m][sidx];
                atomicAdd(&g_agg[src * 64 + 16 + k * 3 + 0], accV[m][sidx][0] + s1 * rv);
                atomicAdd(&g_agg[src * 64 + 16 + k * 3 + 1], accV[m][sidx][1] + s2 * rv);
                atomicAdd(&g_agg[src * 64 + 16 + k * 3 + 2], accV[m][sidx][2] + s3 * rv);
            }
            if (q == 0) atomicAdd(&g_cnt[src], 1.0f);
        }
    }
}

// ---------------- kernel 3: mean + residual + BN stats ----------------
__global__ __launch_bounds__(256) void k_stats(const float* __restrict__ node_attr) {
    __shared__ float sstat[48];
    int tid = threadIdx.x;
    if (tid < 48) sstat[tid] = 0.0f;
    __syncthreads();

    int n = blockIdx.x * 16 + (tid >> 4);
    int q = tid & 15;
    if (n < N_NODES) {
        float inv = 1.0f / fmaxf(g_cnt[n], 1.0f);
        float4 ag = *(const float4*)&g_agg[n * 64 + q * 4];
        float4 na = *(const float4*)&node_attr[n * 64 + q * 4];
        float o[4] = {fmaf(ag.x, inv, na.x), fmaf(ag.y, inv, na.y),
                      fmaf(ag.z, inv, na.z), fmaf(ag.w, inv, na.w)};
        *(float4*)&g_out[n * 64 + q * 4] = make_float4(o[0], o[1], o[2], o[3]);
        if (q < 4) {
#pragma unroll
            for (int t = 0; t < 4; t++) {
                atomicAdd(&sstat[q * 4 + t], o[t]);
                atomicAdd(&sstat[16 + q * 4 + t], o[t] * o[t]);
            }
        } else {
#pragma unroll
            for (int t = 0; t < 4; t++) {
                int k = (q * 4 + t - 16) / 3;
                atomicAdd(&sstat[32 + k], o[t] * o[t]);
            }
        }
    }
    __syncthreads();
    if (tid < 48) atomicAdd(&g_stats[tid], sstat[tid]);
}

// ---------------- kernel 4: finalize ----------------
__global__ void k_finalize(const float* __restrict__ bn_weight) {
    int t = threadIdx.x;
    if (t < 16) {
        float mean = g_stats[t] * (1.0f / N_NODES);
        float var = g_stats[16 + t] * (1.0f / N_NODES) - mean * mean;
        g_norm[t] = mean;
        g_norm[16 + t] = bn_weight[t] * rsqrtf(var + BN_EPS);
        float fn = g_stats[32 + t] * (1.0f / (3.0f * N_NODES));
        g_norm[32 + t] = bn_weight[16 + t] * rsqrtf(fn + BN_EPS);
    }
}

// ---------------- kernel 5: normalize ----------------
__global__ void k_norm(const float* __restrict__ bn_bias, float* __restrict__ out) {
    int idx = blockIdx.x * blockDim.x + threadIdx.x;
    if (idx >= N_NODES * 64) return;
    int f = idx & 63;
    float o = g_out[idx];
    if (f < 16)
        out[idx] = (o - g_norm[f]) * g_norm[16 + f] + bn_bias[f];
    else
        out[idx] = o * g_norm[32 + (f - 16) / 3];
}

// ---------------- launch ----------------
extern "C" void kernel_launch(void* const* d_in, const int* in_sizes, int n_in,
                              void* d_out, int out_size) {
    const float* node_attr = (const float*)d_in[0];
    const float* edge_attr = (const float*)d_in[1];
    const float* edge_sh = (const float*)d_in[2];
    const float* w1 = (const float*)d_in[3];
    const float* b1 = (const float*)d_in[4];
    const float* w2 = (const float*)d_in[5];
    const float* b2 = (const float*)d_in[6];
    const float* bnw = (const float*)d_in[7];
    const float* bnb = (const float*)d_in[8];
    const int* eidx = (const int*)d_in[9];
    float* out = (float*)d_out;

    const int SMEM_G1 = (64 * HS + 64 * 64) * 4;
    cudaFuncSetAttribute(k_gemm1, cudaFuncAttributeMaxDynamicSharedMemorySize, SMEM_G1);
    cudaFuncSetAttribute(k_tp, cudaFuncAttributeMaxDynamicSharedMemorySize, SMEM_TP);

    k_zero<<<512, 256>>>();
    k_wsplit<<<256, 256>>>(w2);
    k_gemm1<<<N_EDGES / 64, 256, SMEM_G1>>>(edge_attr, w1, b1);
    k_tp<<<(N_EDGES + 127) / 128, 256, SMEM_TP>>>(node_attr, edge_sh, b2, eidx);
    k_stats<<<(N_NODES + 15) / 16, 256>>>(node_attr);
    k_finalize<<<1, 32>>>(bnw);
    k_norm<<<(N_NODES * 64 + 255) / 256, 256>>>(bnb, out);
}